// round 4
// baseline (speedup 1.0000x reference)
#include <cuda_runtime.h>

#define NN 50000
#define DD 128

// Scratch (device globals: no allocation allowed)
__device__ float g_agg[NN * DD];
__device__ float g_h[NN * DD];
__device__ float g_cnt[NN];
__device__ int   g_idx64;

// ---------------------------------------------------------------------------
// Detect whether edge_index is int64 (hi words all zero) or int32.
// ---------------------------------------------------------------------------
__global__ void detect_kernel(const unsigned int* __restrict__ ei) {
    __shared__ int any_nonzero;
    if (threadIdx.x == 0) any_nonzero = 0;
    __syncthreads();
    if (ei[2 * threadIdx.x + 1] != 0u) atomicOr(&any_nonzero, 1);
    __syncthreads();
    if (threadIdx.x == 0) g_idx64 = (any_nonzero == 0) ? 1 : 0;
}

// ---------------------------------------------------------------------------
// Zero agg (and counts for layer 1)
// ---------------------------------------------------------------------------
__global__ void zero_kernel(int with_cnt) {
    int i = blockIdx.x * blockDim.x + threadIdx.x;
    if (i < NN * DD / 4) ((float4*)g_agg)[i] = make_float4(0.f, 0.f, 0.f, 0.f);
    if (with_cnt && i < NN) g_cnt[i] = 0.f;
}

// ---------------------------------------------------------------------------
// Edge gather: one warp per edge. lane l moves float4 at col 4l.
// Scatter uses vectorized red.global.add.v4.f32 (sm_90+): 1 RED per 16B.
// ---------------------------------------------------------------------------
__global__ void gather_kernel(const void* __restrict__ ei, int E,
                              const float* __restrict__ xin, int do_cnt) {
    unsigned gt = blockIdx.x * blockDim.x + threadIdx.x;
    unsigned w  = gt >> 5;
    int lane    = threadIdx.x & 31;
    if (w >= (unsigned)E) return;

    int src, dst;
    if (g_idx64) {
        const long long* q = (const long long*)ei;
        src = (int)q[w];
        dst = (int)q[w + (unsigned)E];
    } else {
        const int* p = (const int*)ei;
        src = p[w];
        dst = p[w + (unsigned)E];
    }

    float4 v = ((const float4*)(xin + (size_t)src * DD))[lane];
    float* a = g_agg + (size_t)dst * DD + lane * 4;
    asm volatile("red.global.add.v4.f32 [%0], {%1, %2, %3, %4};"
                 :: "l"(a), "f"(v.x), "f"(v.y), "f"(v.z), "f"(v.w)
                 : "memory");
    if (do_cnt && lane == 0) atomicAdd(&g_cnt[dst], 1.0f);
}

// ---------------------------------------------------------------------------
// JAX threefry2x32-20 core, key = (0, 42).
// ---------------------------------------------------------------------------
__device__ __forceinline__ unsigned rotl32(unsigned x, int r) {
    return (x << r) | (x >> (32 - r));
}

__device__ __forceinline__ void threefry2x32(unsigned c0, unsigned c1,
                                             unsigned& o0, unsigned& o1) {
    const unsigned k0 = 0u, k1 = 42u;
    const unsigned k2 = k0 ^ k1 ^ 0x1BD11BDAu;
    unsigned x0 = c0 + k0;
    unsigned x1 = c1 + k1;

#define TF_ROUND(r) do { x0 += x1; x1 = rotl32(x1, (r)); x1 ^= x0; } while (0)
#define TF_BLOCK_A  do { TF_ROUND(13); TF_ROUND(15); TF_ROUND(26); TF_ROUND(6);  } while (0)
#define TF_BLOCK_B  do { TF_ROUND(17); TF_ROUND(29); TF_ROUND(16); TF_ROUND(24); } while (0)

    TF_BLOCK_A; x0 += k1; x1 += k2 + 1u;
    TF_BLOCK_B; x0 += k2; x1 += k0 + 2u;
    TF_BLOCK_A; x0 += k0; x1 += k1 + 3u;
    TF_BLOCK_B; x0 += k1; x1 += k2 + 4u;
    TF_BLOCK_A; x0 += k2; x1 += k0 + 5u;

#undef TF_ROUND
#undef TF_BLOCK_A
#undef TF_BLOCK_B

    o0 = x0; o1 = x1;
}

// Partitionable threefry, float64 uniform (x64-enabled JAX), key(42):
//   counter (hi,lo) = (0, f); bits64 = (out0<<32)|out1
//   u = bitcast((bits64 >> 12) | 0x3FF0...) - 1.0 ; keep if u < 0.8
__device__ __forceinline__ float drop_mask(unsigned f) {
    unsigned o0, o1;
    threefry2x32(0u, f, o0, o1);
    unsigned long long b =
        ((unsigned long long)o0 << 32) | (unsigned long long)o1;
    b = (b >> 12) | 0x3FF0000000000000ULL;
    double u = __longlong_as_double((long long)b) - 1.0;
    return (u < 0.8) ? 1.25f : 0.0f;
}

// ---------------------------------------------------------------------------
// Node update: out = (agg/max(cnt,1)) @ Wl^T + xin @ Wr^T + b
// Optional fused relu + dropout (layer 1).
// ---------------------------------------------------------------------------
template <bool DROP>
__global__ void node_kernel(const float* __restrict__ xin,
                            const float* __restrict__ Wl,
                            const float* __restrict__ Wr,
                            const float* __restrict__ bias,
                            float* __restrict__ out) {
    extern __shared__ float sm[];
    float* wls = sm;                 // [128][132] : wls[k*132+j] = Wl[j*128+k]
    float* wrs = wls + 128 * 132;    // [128][132]
    float* ms  = wrs + 128 * 132;    // [32][128] mean rows
    float* xs  = ms + 32 * 128;      // [32][128] x rows

    int t = threadIdx.x;

    for (int i = t; i < 128 * 128; i += 256) {
        int j = i >> 7, k = i & 127;
        wls[k * 132 + j] = Wl[i];
        wrs[k * 132 + j] = Wr[i];
    }

    int row0 = blockIdx.x * 32;
    for (int i = t; i < 1024; i += 256) {
        int r = i >> 5, c4 = i & 31;
        int row = row0 + r;
        float4 xv = make_float4(0.f, 0.f, 0.f, 0.f);
        float4 mv = xv;
        if (row < NN) {
            xv = ((const float4*)(xin + (size_t)row * DD))[c4];
            float4 av = ((const float4*)(g_agg + (size_t)row * DD))[c4];
            float invc = 1.0f / fmaxf(g_cnt[row], 1.0f);
            mv = make_float4(av.x * invc, av.y * invc, av.z * invc, av.w * invc);
        }
        ((float4*)xs)[i] = xv;
        ((float4*)ms)[i] = mv;
    }
    __syncthreads();

    int jq = t & 31;
    int rg = t >> 5;

    float acc[4][4];
#pragma unroll
    for (int a = 0; a < 4; a++)
#pragma unroll
        for (int b = 0; b < 4; b++) acc[a][b] = 0.f;

#pragma unroll 4
    for (int k = 0; k < 128; k++) {
        float4 wl = *(const float4*)(wls + k * 132 + 4 * jq);
        float4 wr = *(const float4*)(wrs + k * 132 + 4 * jq);
#pragma unroll
        for (int rr = 0; rr < 4; rr++) {
            int r = rg + rr * 8;
            float m = ms[r * 128 + k];
            float x = xs[r * 128 + k];
            acc[rr][0] += m * wl.x;  acc[rr][1] += m * wl.y;
            acc[rr][2] += m * wl.z;  acc[rr][3] += m * wl.w;
            acc[rr][0] += x * wr.x;  acc[rr][1] += x * wr.y;
            acc[rr][2] += x * wr.z;  acc[rr][3] += x * wr.w;
        }
    }

    float4 bv = *(const float4*)(bias + 4 * jq);
#pragma unroll
    for (int rr = 0; rr < 4; rr++) {
        int row = row0 + rg + rr * 8;
        if (row >= NN) continue;
        float4 o;
        o.x = acc[rr][0] + bv.x;
        o.y = acc[rr][1] + bv.y;
        o.z = acc[rr][2] + bv.z;
        o.w = acc[rr][3] + bv.w;
        if (DROP) {
            unsigned base = (unsigned)row * DD + 4 * jq;
            o.x = fmaxf(o.x, 0.f) * drop_mask(base + 0);
            o.y = fmaxf(o.y, 0.f) * drop_mask(base + 1);
            o.z = fmaxf(o.z, 0.f) * drop_mask(base + 2);
            o.w = fmaxf(o.w, 0.f) * drop_mask(base + 3);
        }
        *(float4*)(out + (size_t)row * DD + 4 * jq) = o;
    }
}

// ---------------------------------------------------------------------------
extern "C" void kernel_launch(void* const* d_in, const int* in_sizes, int n_in,
                              void* d_out, int out_size) {
    const float* x   = (const float*)d_in[0];
    const void*  ei  = d_in[1];
    const float* W1l = (const float*)d_in[2];
    const float* W1r = (const float*)d_in[3];
    const float* b1  = (const float*)d_in[4];
    const float* W2l = (const float*)d_in[5];
    const float* W2r = (const float*)d_in[6];
    const float* b2  = (const float*)d_in[7];
    float* out = (float*)d_out;

    int E = in_sizes[1] / 2;

    const int SMEM = (2 * 128 * 132 + 2 * 32 * 128) * (int)sizeof(float);
    cudaFuncSetAttribute(node_kernel<true>,
                         cudaFuncAttributeMaxDynamicSharedMemorySize, SMEM);
    cudaFuncSetAttribute(node_kernel<false>,
                         cudaFuncAttributeMaxDynamicSharedMemorySize, SMEM);

    float* h_ptr = nullptr;
    cudaGetSymbolAddress((void**)&h_ptr, g_h);

    int zero_blocks   = (NN * DD / 4 + 255) / 256;
    int gather_blocks = (int)(((long long)E * 32 + 255) / 256);
    int node_blocks   = (NN + 31) / 32;

    detect_kernel<<<1, 256>>>((const unsigned int*)ei);

    // ----- Layer 1 -----
    zero_kernel<<<zero_blocks, 256>>>(1);
    gather_kernel<<<gather_blocks, 256>>>(ei, E, x, 1);
    node_kernel<true><<<node_blocks, 256, SMEM>>>(x, W1l, W1r, b1, h_ptr);

    // ----- Layer 2 -----
    zero_kernel<<<zero_blocks, 256>>>(0);
    gather_kernel<<<gather_blocks, 256>>>(ei, E, h_ptr, 0);
    node_kernel<false><<<node_blocks, 256, SMEM>>>(h_ptr, W2l, W2r, b2, out);
}

// round 5
// speedup vs baseline: 1.2325x; 1.2325x over previous
#include <cuda_runtime.h>

#define NN 50000
#define DD 128

// Scratch (device globals: no allocation allowed)
__device__ float g_agg[NN * DD];
__device__ float g_h[NN * DD];
__device__ float g_cnt[NN];
__device__ float g_wt[2][256 * 128];   // [layer][k][j] : rows 0..127 Wl^T, 128..255 Wr^T
__device__ int   g_idx64;

// ---------------------------------------------------------------------------
// Detect whether edge_index is int64 (hi words all zero) or int32.
// ---------------------------------------------------------------------------
__global__ void detect_kernel(const unsigned int* __restrict__ ei) {
    __shared__ int any_nonzero;
    if (threadIdx.x == 0) any_nonzero = 0;
    __syncthreads();
    if (ei[2 * threadIdx.x + 1] != 0u) atomicOr(&any_nonzero, 1);
    __syncthreads();
    if (threadIdx.x == 0) g_idx64 = (any_nonzero == 0) ? 1 : 0;
}

// ---------------------------------------------------------------------------
// Pre-transpose all four weight matrices into g_wt.
// grid (128, 4), 128 threads. y: 0=W1l,1=W1r,2=W2l,3=W2r.
// ---------------------------------------------------------------------------
__global__ void transpose_kernel(const float* __restrict__ W1l,
                                 const float* __restrict__ W1r,
                                 const float* __restrict__ W2l,
                                 const float* __restrict__ W2r) {
    int k = blockIdx.x;          // 0..127
    int y = blockIdx.y;          // 0..3
    int j = threadIdx.x;         // 0..127
    const float* W = (y == 0) ? W1l : (y == 1) ? W1r : (y == 2) ? W2l : W2r;
    int layer = y >> 1;
    int krow  = k + (y & 1) * 128;
    g_wt[layer][krow * 128 + j] = W[j * 128 + k];
}

// ---------------------------------------------------------------------------
// Zero agg (and counts for layer 1)
// ---------------------------------------------------------------------------
__global__ void zero_kernel(int with_cnt) {
    int i = blockIdx.x * blockDim.x + threadIdx.x;
    if (i < NN * DD / 4) ((float4*)g_agg)[i] = make_float4(0.f, 0.f, 0.f, 0.f);
    if (with_cnt && i < NN) g_cnt[i] = 0.f;
}

// ---------------------------------------------------------------------------
// Edge gather: one warp per edge. lane l moves float4 at col 4l.
// Scatter via red.global.add.v4.f32.
// ---------------------------------------------------------------------------
__global__ void gather_kernel(const void* __restrict__ ei, int E,
                              const float* __restrict__ xin, int do_cnt) {
    unsigned gt = blockIdx.x * blockDim.x + threadIdx.x;
    unsigned w  = gt >> 5;
    int lane    = threadIdx.x & 31;
    if (w >= (unsigned)E) return;

    int src, dst;
    if (g_idx64) {
        const long long* q = (const long long*)ei;
        src = (int)q[w];
        dst = (int)q[w + (unsigned)E];
    } else {
        const int* p = (const int*)ei;
        src = p[w];
        dst = p[w + (unsigned)E];
    }

    float4 v = __ldg(((const float4*)(xin + (size_t)src * DD)) + lane);
    float* a = g_agg + (size_t)dst * DD + lane * 4;
    asm volatile("red.global.add.v4.f32 [%0], {%1, %2, %3, %4};"
                 :: "l"(a), "f"(v.x), "f"(v.y), "f"(v.z), "f"(v.w)
                 : "memory");
    if (do_cnt && lane == 0) atomicAdd(&g_cnt[dst], 1.0f);
}

// ---------------------------------------------------------------------------
// JAX threefry2x32-20, key=(0,42), partitionable, float64 uniform:
//   counter (0, f); bits64 = (out0<<32)|out1
//   keep iff bitcast((bits64>>12)|0x3FF0...)-1.0 < 0.8
// ---------------------------------------------------------------------------
__device__ __forceinline__ unsigned rotl32(unsigned x, int r) {
    return (x << r) | (x >> (32 - r));
}

__device__ __forceinline__ float drop_mask(unsigned f) {
    const unsigned k0 = 0u, k1 = 42u;
    const unsigned k2 = k0 ^ k1 ^ 0x1BD11BDAu;
    unsigned x0 = 0u + k0;
    unsigned x1 = f + k1;

#define TF_ROUND(r) do { x0 += x1; x1 = rotl32(x1, (r)); x1 ^= x0; } while (0)
#define TF_BLOCK_A  do { TF_ROUND(13); TF_ROUND(15); TF_ROUND(26); TF_ROUND(6);  } while (0)
#define TF_BLOCK_B  do { TF_ROUND(17); TF_ROUND(29); TF_ROUND(16); TF_ROUND(24); } while (0)

    TF_BLOCK_A; x0 += k1; x1 += k2 + 1u;
    TF_BLOCK_B; x0 += k2; x1 += k0 + 2u;
    TF_BLOCK_A; x0 += k0; x1 += k1 + 3u;
    TF_BLOCK_B; x0 += k1; x1 += k2 + 4u;
    TF_BLOCK_A; x0 += k2; x1 += k0 + 5u;

#undef TF_ROUND
#undef TF_BLOCK_A
#undef TF_BLOCK_B

    unsigned long long b =
        ((unsigned long long)x0 << 32) | (unsigned long long)x1;
    b = (b >> 12) | 0x3FF0000000000000ULL;
    double u = __longlong_as_double((long long)b) - 1.0;
    return (u < 0.8) ? 1.25f : 0.0f;
}

// ---------------------------------------------------------------------------
// Node update: out = [mean | x] @ [Wl;Wr]^T + b  (K = 256 fused loop)
// 64 rows per block, 256 threads. Weights from L1-cached global W^T.
// Optional fused relu + dropout (layer 1).
// ---------------------------------------------------------------------------
__device__ __forceinline__ void fma4(float4& a, float s, const float4& w) {
    a.x = fmaf(s, w.x, a.x);
    a.y = fmaf(s, w.y, a.y);
    a.z = fmaf(s, w.z, a.z);
    a.w = fmaf(s, w.w, a.w);
}

template <bool DROP>
__global__ void __launch_bounds__(256, 1)
node_kernel(const float* __restrict__ xin,
            const float* __restrict__ wt,     // [256][128] k-major
            const float* __restrict__ bias,
            float* __restrict__ out) {
    extern __shared__ float ss[];  // [64][256] : cols 0..127 mean, 128..255 x

    int t = threadIdx.x;
    int row0 = blockIdx.x * 64;

    // Stage 64 rows of [mean | x]
    for (int i = t; i < 4096; i += 256) {   // 64 rows * 64 float4
        int r = i >> 6, c4 = i & 63;
        int row = row0 + r;
        float4 v = make_float4(0.f, 0.f, 0.f, 0.f);
        if (row < NN) {
            if (c4 < 32) {
                float4 av = __ldg(((const float4*)(g_agg + (size_t)row * DD)) + c4);
                float invc = 1.0f / fmaxf(g_cnt[row], 1.0f);
                v = make_float4(av.x * invc, av.y * invc, av.z * invc, av.w * invc);
            } else {
                v = __ldg(((const float4*)(xin + (size_t)row * DD)) + (c4 - 32));
            }
        }
        ((float4*)ss)[i] = v;
    }
    __syncthreads();

    int jq = t & 31;   // output col quad
    int rg = t >> 5;   // row group: rows rg + 8*rr

    float4 acc[8];
#pragma unroll
    for (int rr = 0; rr < 8; rr++) acc[rr] = make_float4(0.f, 0.f, 0.f, 0.f);

#pragma unroll 2
    for (int k4 = 0; k4 < 64; k4++) {
        const float* wk = wt + (4 * k4) * 128 + 4 * jq;
        float4 w0 = __ldg((const float4*)(wk + 0 * 128));
        float4 w1 = __ldg((const float4*)(wk + 1 * 128));
        float4 w2 = __ldg((const float4*)(wk + 2 * 128));
        float4 w3 = __ldg((const float4*)(wk + 3 * 128));
#pragma unroll
        for (int rr = 0; rr < 8; rr++) {
            int r = rg + rr * 8;
            float4 s = ((const float4*)(ss + r * 256))[k4];
            fma4(acc[rr], s.x, w0);
            fma4(acc[rr], s.y, w1);
            fma4(acc[rr], s.z, w2);
            fma4(acc[rr], s.w, w3);
        }
    }

    float4 bv = __ldg(((const float4*)bias) + jq);
#pragma unroll
    for (int rr = 0; rr < 8; rr++) {
        int row = row0 + rg + rr * 8;
        if (row >= NN) continue;
        float4 o;
        o.x = acc[rr].x + bv.x;
        o.y = acc[rr].y + bv.y;
        o.z = acc[rr].z + bv.z;
        o.w = acc[rr].w + bv.w;
        if (DROP) {
            unsigned base = (unsigned)row * DD + 4 * jq;
            o.x = fmaxf(o.x, 0.f) * drop_mask(base + 0);
            o.y = fmaxf(o.y, 0.f) * drop_mask(base + 1);
            o.z = fmaxf(o.z, 0.f) * drop_mask(base + 2);
            o.w = fmaxf(o.w, 0.f) * drop_mask(base + 3);
        }
        *(float4*)(out + (size_t)row * DD + 4 * jq) = o;
    }
}

// ---------------------------------------------------------------------------
extern "C" void kernel_launch(void* const* d_in, const int* in_sizes, int n_in,
                              void* d_out, int out_size) {
    const float* x   = (const float*)d_in[0];
    const void*  ei  = d_in[1];
    const float* W1l = (const float*)d_in[2];
    const float* W1r = (const float*)d_in[3];
    const float* b1  = (const float*)d_in[4];
    const float* W2l = (const float*)d_in[5];
    const float* W2r = (const float*)d_in[6];
    const float* b2  = (const float*)d_in[7];
    float* out = (float*)d_out;

    int E = in_sizes[1] / 2;

    const int SMEM = 64 * 256 * (int)sizeof(float);  // 65536
    cudaFuncSetAttribute(node_kernel<true>,
                         cudaFuncAttributeMaxDynamicSharedMemorySize, SMEM);
    cudaFuncSetAttribute(node_kernel<false>,
                         cudaFuncAttributeMaxDynamicSharedMemorySize, SMEM);

    float* h_ptr  = nullptr;
    float* wt_ptr = nullptr;
    cudaGetSymbolAddress((void**)&h_ptr, g_h);
    cudaGetSymbolAddress((void**)&wt_ptr, g_wt);
    const float* wt1 = wt_ptr;
    const float* wt2 = wt_ptr + 256 * 128;

    int zero_blocks   = (NN * DD / 4 + 255) / 256;
    int gather_blocks = (int)(((long long)E * 32 + 255) / 256);
    int node_blocks   = (NN + 63) / 64;

    detect_kernel<<<1, 256>>>((const unsigned int*)ei);
    transpose_kernel<<<dim3(128, 4), 128>>>(W1l, W1r, W2l, W2r);

    // ----- Layer 1 -----
    zero_kernel<<<zero_blocks, 256>>>(1);
    gather_kernel<<<gather_blocks, 256>>>(ei, E, x, 1);
    node_kernel<true><<<node_blocks, 256, SMEM>>>(x, wt1, b1, h_ptr);

    // ----- Layer 2 -----
    zero_kernel<<<zero_blocks, 256>>>(0);
    gather_kernel<<<gather_blocks, 256>>>(ei, E, h_ptr, 0);
    node_kernel<false><<<node_blocks, 256, SMEM>>>(h_ptr, wt2, b2, out);
}

// round 6
// speedup vs baseline: 1.5115x; 1.2264x over previous
#include <cuda_runtime.h>

#define NN 50000
#define DD 128
#define EMAX 800000

// Scratch (device globals: no allocation allowed)
__device__ float g_mean[NN * DD];
__device__ float g_h[NN * DD];
__device__ float g_wt[2][256 * 128];   // [layer][k][j] : rows 0..127 Wl^T, 128..255 Wr^T
__device__ int   g_deg[NN];
__device__ int   g_cur[NN];
__device__ int   g_rowptr[NN + 1];
__device__ int   g_esrc[EMAX];
__device__ int   g_idx64;

// ---------------------------------------------------------------------------
// Detect whether edge_index is int64 (hi words all zero) or int32.
// ---------------------------------------------------------------------------
__global__ void detect_kernel(const unsigned int* __restrict__ ei) {
    __shared__ int any_nonzero;
    if (threadIdx.x == 0) any_nonzero = 0;
    __syncthreads();
    if (ei[2 * threadIdx.x + 1] != 0u) atomicOr(&any_nonzero, 1);
    __syncthreads();
    if (threadIdx.x == 0) g_idx64 = (any_nonzero == 0) ? 1 : 0;
}

// ---------------------------------------------------------------------------
// Pre-transpose weights into g_wt. grid (128,4), 128 thr.
// ---------------------------------------------------------------------------
__global__ void transpose_kernel(const float* __restrict__ W1l,
                                 const float* __restrict__ W1r,
                                 const float* __restrict__ W2l,
                                 const float* __restrict__ W2r) {
    int k = blockIdx.x, y = blockIdx.y, j = threadIdx.x;
    const float* W = (y == 0) ? W1l : (y == 1) ? W1r : (y == 2) ? W2l : W2r;
    g_wt[y >> 1][(k + (y & 1) * 128) * 128 + j] = W[j * 128 + k];
}

// ---------------------------------------------------------------------------
// CSR build
// ---------------------------------------------------------------------------
__global__ void zero_small_kernel() {
    int i = blockIdx.x * blockDim.x + threadIdx.x;
    if (i < NN) { g_deg[i] = 0; g_cur[i] = 0; }
}

__device__ __forceinline__ int load_dst(const void* ei, unsigned e, unsigned E) {
    if (g_idx64) return (int)((const long long*)ei)[e + E];
    return ((const int*)ei)[e + E];
}
__device__ __forceinline__ int load_src(const void* ei, unsigned e, unsigned E) {
    if (g_idx64) return (int)((const long long*)ei)[e];
    return ((const int*)ei)[e];
}

__global__ void hist_kernel(const void* __restrict__ ei, int E) {
    unsigned e = blockIdx.x * blockDim.x + threadIdx.x;
    if (e >= (unsigned)E) return;
    atomicAdd(&g_deg[load_dst(ei, e, E)], 1);
}

__global__ void scan_kernel() {
    __shared__ int sp[1024];
    int t = threadIdx.x;
    const int CH = (NN + 1023) / 1024;  // 49
    int base = t * CH;
    int s = 0;
    for (int i = 0; i < CH; i++) {
        int idx = base + i;
        if (idx < NN) s += g_deg[idx];
    }
    sp[t] = s;
    __syncthreads();
    for (int off = 1; off < 1024; off <<= 1) {
        int v = (t >= off) ? sp[t - off] : 0;
        __syncthreads();
        sp[t] += v;
        __syncthreads();
    }
    int run = (t == 0) ? 0 : sp[t - 1];
    for (int i = 0; i < CH; i++) {
        int idx = base + i;
        if (idx < NN) { g_rowptr[idx] = run; run += g_deg[idx]; }
    }
    if (t == 1023) g_rowptr[NN] = run;
}

__global__ void scatter_kernel(const void* __restrict__ ei, int E) {
    unsigned e = blockIdx.x * blockDim.x + threadIdx.x;
    if (e >= (unsigned)E) return;
    int src = load_src(ei, e, E);
    int dst = load_dst(ei, e, E);
    int pos = g_rowptr[dst] + atomicAdd(&g_cur[dst], 1);
    g_esrc[pos] = src;
}

// ---------------------------------------------------------------------------
// Aggregation: one warp per destination node. Registers accumulate, fused
// mean division, single vector store. No atomics, no zero-init.
// ---------------------------------------------------------------------------
__global__ void __launch_bounds__(256)
agg_kernel(const float* __restrict__ xin) {
    int warp = (blockIdx.x * blockDim.x + threadIdx.x) >> 5;
    int lane = threadIdx.x & 31;
    if (warp >= NN) return;

    int start = g_rowptr[warp];
    int end   = g_rowptr[warp + 1];

    float4 acc = make_float4(0.f, 0.f, 0.f, 0.f);
    int j = start;
    for (; j + 4 <= end; j += 4) {
        int s0 = g_esrc[j + 0], s1 = g_esrc[j + 1];
        int s2 = g_esrc[j + 2], s3 = g_esrc[j + 3];
        float4 v0 = __ldg(((const float4*)(xin + (size_t)s0 * DD)) + lane);
        float4 v1 = __ldg(((const float4*)(xin + (size_t)s1 * DD)) + lane);
        float4 v2 = __ldg(((const float4*)(xin + (size_t)s2 * DD)) + lane);
        float4 v3 = __ldg(((const float4*)(xin + (size_t)s3 * DD)) + lane);
        acc.x += v0.x + v1.x + v2.x + v3.x;
        acc.y += v0.y + v1.y + v2.y + v3.y;
        acc.z += v0.z + v1.z + v2.z + v3.z;
        acc.w += v0.w + v1.w + v2.w + v3.w;
    }
    for (; j < end; j++) {
        int s = g_esrc[j];
        float4 v = __ldg(((const float4*)(xin + (size_t)s * DD)) + lane);
        acc.x += v.x; acc.y += v.y; acc.z += v.z; acc.w += v.w;
    }

    float inv = 1.0f / fmaxf((float)(end - start), 1.0f);
    acc.x *= inv; acc.y *= inv; acc.z *= inv; acc.w *= inv;
    ((float4*)(g_mean + (size_t)warp * DD))[lane] = acc;
}

// ---------------------------------------------------------------------------
// JAX threefry2x32-20, key=(0,42), partitionable, float64 uniform.
// ---------------------------------------------------------------------------
__device__ __forceinline__ unsigned rotl32(unsigned x, int r) {
    return (x << r) | (x >> (32 - r));
}

__device__ __forceinline__ float drop_mask(unsigned f) {
    const unsigned k0 = 0u, k1 = 42u;
    const unsigned k2 = k0 ^ k1 ^ 0x1BD11BDAu;
    unsigned x0 = 0u + k0;
    unsigned x1 = f + k1;

#define TF_ROUND(r) do { x0 += x1; x1 = rotl32(x1, (r)); x1 ^= x0; } while (0)
#define TF_BLOCK_A  do { TF_ROUND(13); TF_ROUND(15); TF_ROUND(26); TF_ROUND(6);  } while (0)
#define TF_BLOCK_B  do { TF_ROUND(17); TF_ROUND(29); TF_ROUND(16); TF_ROUND(24); } while (0)

    TF_BLOCK_A; x0 += k1; x1 += k2 + 1u;
    TF_BLOCK_B; x0 += k2; x1 += k0 + 2u;
    TF_BLOCK_A; x0 += k0; x1 += k1 + 3u;
    TF_BLOCK_B; x0 += k1; x1 += k2 + 4u;
    TF_BLOCK_A; x0 += k2; x1 += k0 + 5u;

#undef TF_ROUND
#undef TF_BLOCK_A
#undef TF_BLOCK_B

    unsigned long long b =
        ((unsigned long long)x0 << 32) | (unsigned long long)x1;
    b = (b >> 12) | 0x3FF0000000000000ULL;
    double u = __longlong_as_double((long long)b) - 1.0;
    return (u < 0.8) ? 1.25f : 0.0f;
}

// ---------------------------------------------------------------------------
// Node update: out = [mean | x] @ [Wl;Wr]^T + b  (K = 256 fused loop)
// ---------------------------------------------------------------------------
__device__ __forceinline__ void fma4(float4& a, float s, const float4& w) {
    a.x = fmaf(s, w.x, a.x);
    a.y = fmaf(s, w.y, a.y);
    a.z = fmaf(s, w.z, a.z);
    a.w = fmaf(s, w.w, a.w);
}

template <bool DROP>
__global__ void __launch_bounds__(256, 1)
node_kernel(const float* __restrict__ xin,
            const float* __restrict__ wt,     // [256][128] k-major
            const float* __restrict__ bias,
            float* __restrict__ out) {
    extern __shared__ float ss[];  // [64][256] : cols 0..127 mean, 128..255 x

    int t = threadIdx.x;
    int row0 = blockIdx.x * 64;

    for (int i = t; i < 4096; i += 256) {   // 64 rows * 64 float4
        int r = i >> 6, c4 = i & 63;
        int row = row0 + r;
        float4 v = make_float4(0.f, 0.f, 0.f, 0.f);
        if (row < NN) {
            if (c4 < 32)
                v = __ldg(((const float4*)(g_mean + (size_t)row * DD)) + c4);
            else
                v = __ldg(((const float4*)(xin + (size_t)row * DD)) + (c4 - 32));
        }
        ((float4*)ss)[i] = v;
    }
    __syncthreads();

    int jq = t & 31;
    int rg = t >> 5;

    float4 acc[8];
#pragma unroll
    for (int rr = 0; rr < 8; rr++) acc[rr] = make_float4(0.f, 0.f, 0.f, 0.f);

#pragma unroll 2
    for (int k4 = 0; k4 < 64; k4++) {
        const float* wk = wt + (4 * k4) * 128 + 4 * jq;
        float4 w0 = __ldg((const float4*)(wk + 0 * 128));
        float4 w1 = __ldg((const float4*)(wk + 1 * 128));
        float4 w2 = __ldg((const float4*)(wk + 2 * 128));
        float4 w3 = __ldg((const float4*)(wk + 3 * 128));
#pragma unroll
        for (int rr = 0; rr < 8; rr++) {
            int r = rg + rr * 8;
            float4 s = ((const float4*)(ss + r * 256))[k4];
            fma4(acc[rr], s.x, w0);
            fma4(acc[rr], s.y, w1);
            fma4(acc[rr], s.z, w2);
            fma4(acc[rr], s.w, w3);
        }
    }

    float4 bv = __ldg(((const float4*)bias) + jq);
#pragma unroll
    for (int rr = 0; rr < 8; rr++) {
        int row = row0 + rg + rr * 8;
        if (row >= NN) continue;
        float4 o;
        o.x = acc[rr].x + bv.x;
        o.y = acc[rr].y + bv.y;
        o.z = acc[rr].z + bv.z;
        o.w = acc[rr].w + bv.w;
        if (DROP) {
            unsigned base = (unsigned)row * DD + 4 * jq;
            o.x = fmaxf(o.x, 0.f) * drop_mask(base + 0);
            o.y = fmaxf(o.y, 0.f) * drop_mask(base + 1);
            o.z = fmaxf(o.z, 0.f) * drop_mask(base + 2);
            o.w = fmaxf(o.w, 0.f) * drop_mask(base + 3);
        }
        *(float4*)(out + (size_t)row * DD + 4 * jq) = o;
    }
}

// ---------------------------------------------------------------------------
extern "C" void kernel_launch(void* const* d_in, const int* in_sizes, int n_in,
                              void* d_out, int out_size) {
    const float* x   = (const float*)d_in[0];
    const void*  ei  = d_in[1];
    const float* W1l = (const float*)d_in[2];
    const float* W1r = (const float*)d_in[3];
    const float* b1  = (const float*)d_in[4];
    const float* W2l = (const float*)d_in[5];
    const float* W2r = (const float*)d_in[6];
    const float* b2  = (const float*)d_in[7];
    float* out = (float*)d_out;

    int E = in_sizes[1] / 2;

    const int SMEM = 64 * 256 * (int)sizeof(float);  // 65536
    cudaFuncSetAttribute(node_kernel<true>,
                         cudaFuncAttributeMaxDynamicSharedMemorySize, SMEM);
    cudaFuncSetAttribute(node_kernel<false>,
                         cudaFuncAttributeMaxDynamicSharedMemorySize, SMEM);

    float* h_ptr  = nullptr;
    float* wt_ptr = nullptr;
    cudaGetSymbolAddress((void**)&h_ptr, g_h);
    cudaGetSymbolAddress((void**)&wt_ptr, g_wt);
    const float* wt1 = wt_ptr;
    const float* wt2 = wt_ptr + 256 * 128;

    int edge_blocks = (E + 255) / 256;
    int agg_blocks  = (NN * 32 + 255) / 256;
    int node_blocks = (NN + 63) / 64;

    // ----- One-time per launch: CSR build + weight transpose -----
    detect_kernel<<<1, 256>>>((const unsigned int*)ei);
    transpose_kernel<<<dim3(128, 4), 128>>>(W1l, W1r, W2l, W2r);
    zero_small_kernel<<<(NN + 255) / 256, 256>>>();
    hist_kernel<<<edge_blocks, 256>>>(ei, E);
    scan_kernel<<<1, 1024>>>();
    scatter_kernel<<<edge_blocks, 256>>>(ei, E);

    // ----- Layer 1 -----
    agg_kernel<<<agg_blocks, 256>>>(x);
    node_kernel<true><<<node_blocks, 256, SMEM>>>(x, wt1, b1, h_ptr);

    // ----- Layer 2 -----
    agg_kernel<<<agg_blocks, 256>>>(h_ptr);
    node_kernel<false><<<node_blocks, 256, SMEM>>>(h_ptr, wt2, b2, out);
}